// round 14
// baseline (speedup 1.0000x reference)
#include <cuda_runtime.h>
#include <cuda_bf16.h>
#include <cuda_fp16.h>

typedef unsigned int       u32;
typedef unsigned long long u64;

// Problem constants
constexpr int Bn  = 2;
constexpr int Tn  = 2048;
constexpr int Cn  = 2048;
constexpr int Hn  = 16;
constexpr int HDn = 128;
constexpr float SCALE = 0.088388347648318447f;   // 1/sqrt(128)
constexpr float EPSv  = 1e-6f;

// ---------------------------------------------------------------------------
// Device-global scratch (all activations fp16)
// ---------------------------------------------------------------------------
__device__ __half g_Qh [(size_t)Bn * Hn * Tn * HDn];  // [B,H,T,hd]
__device__ __half g_Kh [(size_t)Bn * Hn * Tn * HDn];
__device__ __half g_Vh [(size_t)Bn * Hn * Tn * HDn];

__device__ __half g_Xh [(size_t)Bn * Tn * Cn];
__device__ __half g_Wh[4][(size_t)Cn * Cn];
__device__ __half g_Ah [(size_t)Bn * Tn * Cn];        // attn out fp16

// ---------------------------------------------------------------------------
// PTX helpers
// ---------------------------------------------------------------------------
__device__ __forceinline__ u32 smem_to_u32(const void* p) {
    u32 a;
    asm("{ .reg .u64 t; cvta.to.shared.u64 t, %1; cvt.u32.u64 %0, t; }"
        : "=r"(a) : "l"(p));
    return a;
}

__device__ __forceinline__ void cp16(u32 saddr, const void* g) {
    asm volatile("cp.async.cg.shared.global [%0], [%1], 16;"
                 :: "r"(saddr), "l"(g) : "memory");
}
#define CP_COMMIT() asm volatile("cp.async.commit_group;" ::: "memory")
#define CP_WAIT(n)  asm volatile("cp.async.wait_group %0;" :: "n"(n) : "memory")

__device__ __forceinline__ void ldsm_x4(u32& r0, u32& r1, u32& r2, u32& r3, u32 addr) {
    asm volatile("ldmatrix.sync.aligned.m8n8.x4.shared.b16 {%0,%1,%2,%3}, [%4];"
                 : "=r"(r0), "=r"(r1), "=r"(r2), "=r"(r3) : "r"(addr));
}
__device__ __forceinline__ void ldsm_x4_t(u32& r0, u32& r1, u32& r2, u32& r3, u32 addr) {
    asm volatile("ldmatrix.sync.aligned.m8n8.x4.trans.shared.b16 {%0,%1,%2,%3}, [%4];"
                 : "=r"(r0), "=r"(r1), "=r"(r2), "=r"(r3) : "r"(addr));
}

__device__ __forceinline__ void mma16816h(float* d, const u32* a, const u32* b) {
    asm volatile(
        "mma.sync.aligned.m16n8k16.row.col.f32.f16.f16.f32 "
        "{%0,%1,%2,%3}, {%4,%5,%6,%7}, {%8,%9}, {%0,%1,%2,%3};"
        : "+f"(d[0]), "+f"(d[1]), "+f"(d[2]), "+f"(d[3])
        : "r"(a[0]), "r"(a[1]), "r"(a[2]), "r"(a[3]), "r"(b[0]), "r"(b[1]));
}

// pack {lo, hi} floats (lo -> bits[15:0])
__device__ __forceinline__ u32 pack_f16x2(float lo, float hi) {
    u32 r;
    asm("cvt.rn.f16x2.f32 %0, %1, %2;" : "=r"(r) : "f"(hi), "f"(lo));
    return r;
}

// ---------------------------------------------------------------------------
// Fused prologue: convert Wq/Wk/Wv/Wo and X to fp16 (single launch).
// ---------------------------------------------------------------------------
__global__ void prep_kernel(const float* __restrict__ x,
                            const float* __restrict__ Wq,
                            const float* __restrict__ Wk,
                            const float* __restrict__ Wv,
                            const float* __restrict__ Wo)
{
    const int nW4 = (Cn * Cn) / 4;
    const int nX4 = (Bn * Tn * Cn) / 4;
    const int total = 4 * nW4 + nX4;
    int g = blockIdx.x * blockDim.x + threadIdx.x;
    if (g >= total) return;

    const float* in;
    __half* dst;
    int i;
    if (g < 4 * nW4) {
        int which = g / nW4;
        i = (g - which * nW4) * 4;
        in = (which == 0) ? Wq : (which == 1) ? Wk : (which == 2) ? Wv : Wo;
        dst = g_Wh[which];
    } else {
        i = (g - 4 * nW4) * 4;
        in = x;
        dst = g_Xh;
    }
    float4 v = *(const float4*)(in + i);
    __half2* p = (__half2*)(dst + i);
    p[0] = __halves2half2(__float2half(v.x), __float2half(v.y));
    p[1] = __halves2half2(__float2half(v.z), __float2half(v.w));
}

// ---------------------------------------------------------------------------
// HMMA fp16 single-pass GEMM: out[m,n] = sum_k A[m,k] * W[n,k]
// Block 128x128, BK=64, 8 warps (2x4), warp tile 64x32,
// 3-stage cp.async pipeline, ONE __syncthreads per chunk, 2 CTAs/SM.
// isOut==0: A=Xh, B=W[z]; out -> Qh (z=0), Kh (z=1), Vh (z=2), [B,H,T,hd]
// isOut==1: A=g_Ah, B=Wo; out -> fp32 OutParam
// ---------------------------------------------------------------------------
constexpr int GBK     = 64;
constexpr int LDS_H   = 72;                       // halves per row (64+8)
constexpr int TILE_B  = 128 * LDS_H * 2;          // 18432
constexpr int STAGE_B = 2 * TILE_B;               // 36864 (A + B)
constexpr int GEMM_SMEM = 3 * STAGE_B;            // 110592
constexpr int NCHUNK  = Cn / GBK;                 // 32

__global__ __launch_bounds__(256, 2)
void gemm_f16(int isOut, float* __restrict__ OutParam)
{
    extern __shared__ char smem[];
    const u32 sbase = smem_to_u32(smem);
    const int tid  = threadIdx.x;
    const int lane = tid & 31;
    const int warp = tid >> 5;
    const int wr   = warp >> 2;     // 0..1
    const int wc   = warp & 3;      // 0..3

    const int mat = isOut ? 3 : blockIdx.z;
    const __half* __restrict__ Am = isOut ? g_Ah : g_Xh;
    const __half* __restrict__ Bm = g_Wh[mat];

    const int mBase = blockIdx.y * 128;
    const int nBase = blockIdx.x * 128;

    float acc[4][4][4];
#pragma unroll
    for (int i = 0; i < 4; i++)
#pragma unroll
        for (int j = 0; j < 4; j++)
#pragma unroll
            for (int r = 0; r < 4; r++) acc[i][j][r] = 0.f;

    const int ldr = tid >> 1;            // row 0..127
    const int ldc = (tid & 1) * 32;      // half-offset 0 / 32

    auto load_chunk = [&](int kc, int s) {
        const u32 sb = sbase + s * STAGE_B;
        const int k0 = kc * GBK;
        {
            const __half* g = Am + (size_t)(mBase + ldr) * Cn + k0 + ldc;
            u32 sa = sb + (ldr * LDS_H + ldc) * 2;
            cp16(sa,      g);
            cp16(sa + 16, g + 8);
            cp16(sa + 32, g + 16);
            cp16(sa + 48, g + 24);
        }
        {
            const __half* g = Bm + (size_t)(nBase + ldr) * Cn + k0 + ldc;
            u32 sa = sb + TILE_B + (ldr * LDS_H + ldc) * 2;
            cp16(sa,      g);
            cp16(sa + 16, g + 8);
            cp16(sa + 32, g + 16);
            cp16(sa + 48, g + 24);
        }
        CP_COMMIT();
    };

    load_chunk(0, 0);
    load_chunk(1, 1);

    int s = 0;                                   // stage of chunk c
    for (int c = 0; c < NCHUNK; c++) {
        if (c + 1 < NCHUNK) { CP_WAIT(1); } else { CP_WAIT(0); }
        __syncthreads();                         // chunk c visible; c-1 done
        if (c + 2 < NCHUNK) {
            int s2 = s + 2; if (s2 >= 3) s2 -= 3;
            load_chunk(c + 2, s2);               // overwrites stage of c-1
        }

        const u32 sA = sbase + s * STAGE_B;
        const u32 sB = sA + TILE_B;

#pragma unroll
        for (int k16 = 0; k16 < 4; k16++) {
            const int col = k16 * 16 + (lane >> 4) * 8;
            const int lrow = (lane & 15);

            u32 af[4][4], bfr[2][4];
#pragma unroll
            for (int mt = 0; mt < 4; mt++) {
                int row = wr * 64 + mt * 16 + lrow;
                u32 off = (u32)(row * LDS_H + col) * 2;
                ldsm_x4(af[mt][0], af[mt][1], af[mt][2], af[mt][3], sA + off);
            }
#pragma unroll
            for (int p = 0; p < 2; p++) {
                int row = wc * 32 + p * 16 + lrow;
                u32 off = (u32)(row * LDS_H + col) * 2;
                ldsm_x4(bfr[p][0], bfr[p][1], bfr[p][2], bfr[p][3], sB + off);
            }
            u32 b0[2][2], b1[2][2];
#pragma unroll
            for (int p = 0; p < 2; p++) {
                b0[p][0] = bfr[p][0]; b0[p][1] = bfr[p][2];
                b1[p][0] = bfr[p][1]; b1[p][1] = bfr[p][3];
            }
#pragma unroll
            for (int mt = 0; mt < 4; mt++)
#pragma unroll
                for (int p = 0; p < 2; p++) {
                    mma16816h(acc[mt][2 * p],     af[mt], b0[p]);
                    mma16816h(acc[mt][2 * p + 1], af[mt], b1[p]);
                }
        }
        if (++s == 3) s = 0;
    }

    // ---- epilogue: two 64-col half passes through smem
    float* sD = (float*)smem;   // [128][68] = 34816 B
    const int c2  = (tid & 31) * 2;
    const int rr0 = tid >> 5;   // 0..7

#pragma unroll
    for (int hc = 0; hc < 2; hc++) {
        __syncthreads();
        if ((wc >> 1) == hc) {
#pragma unroll
            for (int mt = 0; mt < 4; mt++)
#pragma unroll
                for (int nt = 0; nt < 4; nt++) {
                    int row = wr * 64 + mt * 16 + (lane >> 2);
                    int col = (wc & 1) * 32 + nt * 8 + (lane & 3) * 2;
                    sD[row * 68 + col + 0]       = acc[mt][nt][0];
                    sD[row * 68 + col + 1]       = acc[mt][nt][1];
                    sD[(row + 8) * 68 + col + 0] = acc[mt][nt][2];
                    sD[(row + 8) * 68 + col + 1] = acc[mt][nt][3];
                }
        }
        __syncthreads();

        if (!isOut) {
            __half* O = (mat == 0) ? g_Qh : (mat == 1) ? g_Kh : g_Vh;
            const int h = blockIdx.x;      // BN == hd == 128
            const int d = hc * 64 + c2;
#pragma unroll 4
            for (int rr = 0; rr < 16; rr++) {
                int r = rr * 8 + rr0;
                int m = mBase + r;
                int b = m >> 11, t = m & (Tn - 1);
                size_t idx = (size_t)((b * Hn + h) * Tn + t) * HDn + d;
                *(u32*)&O[idx] = pack_f16x2(sD[r * 68 + c2], sD[r * 68 + c2 + 1]);
            }
        } else {
#pragma unroll 4
            for (int rr = 0; rr < 16; rr++) {
                int r = rr * 8 + rr0;
                int m = mBase + r;
                float2 v = make_float2(sD[r * 68 + c2], sD[r * 68 + c2 + 1]);
                *(float2*)&OutParam[(size_t)m * Cn + nBase + hc * 64 + c2] = v;
            }
        }
    }
}

// ---------------------------------------------------------------------------
// HMMA fused relu-attention, fp16 single pass, 3-stage K/V pipeline,
// one __syncthreads per kt. Q fragments hoisted out of the kt loop.
// Block: 128 q-rows x (b,h). 8 warps x 16 q-rows. 64-row K/V tiles.
// ---------------------------------------------------------------------------
constexpr int AT_STR  = 136;
constexpr int AT_Q_B  = 128 * AT_STR * 2;                 // 34816
constexpr int AT_KV_B = 64 * AT_STR * 2;                  // 17408
constexpr int AT_ST_B = 2 * AT_KV_B;                      // 34816 (K+V)
constexpr int ATTN_SMEM = AT_Q_B + 3 * AT_ST_B;           // 139264

__global__ __launch_bounds__(256, 1)
void attn_hmma()
{
    extern __shared__ char smem[];
    const u32 sQ  = smem_to_u32(smem);
    const u32 sKV = sQ + AT_Q_B;

    const int tid  = threadIdx.x;
    const int lane = tid & 31;
    const int w    = tid >> 5;

    const int qt  = (gridDim.x - 1) - blockIdx.x;
    const int bh  = blockIdx.y;
    const int qg0 = qt * 128;

    const __half* Qg = g_Qh + ((size_t)bh * Tn + qg0) * HDn;
    const __half* Kg = g_Kh + (size_t)bh * Tn * HDn;
    const __half* Vg = g_Vh + (size_t)bh * Tn * HDn;

    auto load_kv = [&](int kt, int st) {
        const u32 sb = sKV + st * AT_ST_B;
        const int kr = tid >> 2, kseg = (tid & 3) * 32;
        const size_t gro = (size_t)(kt * 64 + kr) * HDn;
        const u32 so = (kr * AT_STR + kseg) * 2;
#pragma unroll
        for (int i = 0; i < 4; i++) {
            int c = i * 8;
            cp16(sb + so + c * 2,            Kg + gro + kseg + c);
            cp16(sb + AT_KV_B + so + c * 2,  Vg + gro + kseg + c);
        }
        CP_COMMIT();
    };

    const int ktmax = 2 * qt + 1;   // >= 1 always

    // ---- prologue: Q, KV0, KV1
    {
        const int r = tid >> 1, cseg = (tid & 1) * 64;
#pragma unroll
        for (int i = 0; i < 8; i++) {
            int col = cseg + i * 8;
            cp16(sQ + (r * AT_STR + col) * 2, Qg + (size_t)r * HDn + col);
        }
        CP_COMMIT();
    }
    load_kv(0, 0);
    load_kv(1, 1);

    CP_WAIT(2);              // Q complete (kv0, kv1 may be pending)
    __syncthreads();

    u32 qf[8][4];
    {
        const int row = w * 16 + (lane & 15);
#pragma unroll
        for (int c16 = 0; c16 < 8; c16++) {
            int col = c16 * 16 + (lane >> 4) * 8;
            u32 off = (u32)(row * AT_STR + col) * 2;
            ldsm_x4(qf[c16][0], qf[c16][1], qf[c16][2], qf[c16][3], sQ + off);
        }
    }

    float o[16][4];
#pragma unroll
    for (int i = 0; i < 16; i++)
#pragma unroll
        for (int r = 0; r < 4; r++) o[i][r] = 0.f;
    float rs0 = 0.f, rs1 = 0.f;

    const int r0 = qg0 + w * 16 + (lane >> 2);
    const int r1 = r0 + 8;

    int st = 0;                                 // stage of tile kt
    for (int kt = 0; kt <= ktmax; kt++) {
        if (kt + 1 <= ktmax) { CP_WAIT(1); } else { CP_WAIT(0); }
        __syncthreads();                        // kt visible; kt-1 done
        if (kt + 2 <= ktmax) {
            int s2 = st + 2; if (s2 >= 3) s2 -= 3;
            load_kv(kt + 2, s2);
        }

        const u32 cK = sKV + st * AT_ST_B;
        const u32 cV = cK + AT_KV_B;

        // ---- S = Q K^T (fp16), warp: 16 x 64
        float s[8][4];
#pragma unroll
        for (int i = 0; i < 8; i++)
#pragma unroll
            for (int r = 0; r < 4; r++) s[i][r] = 0.f;

#pragma unroll
        for (int c16 = 0; c16 < 8; c16++) {
            u32 kb[4][4];
#pragma unroll
            for (int np = 0; np < 4; np++) {
                int row = np * 16 + (lane & 15);
                int col = c16 * 16 + (lane >> 4) * 8;
                u32 off = (u32)(row * AT_STR + col) * 2;
                ldsm_x4(kb[np][0], kb[np][1], kb[np][2], kb[np][3], cK + off);
            }
            u32 b2[8][2];
#pragma unroll
            for (int np = 0; np < 4; np++) {
                b2[2 * np][0]     = kb[np][0]; b2[2 * np][1]     = kb[np][2];
                b2[2 * np + 1][0] = kb[np][1]; b2[2 * np + 1][1] = kb[np][3];
            }
#pragma unroll
            for (int t = 0; t < 8; t++) mma16816h(s[t], qf[c16], b2[t]);
        }

        // ---- relu + mask + rowsum; pack as fp16 A-frags
        const bool diag = (kt >= 2 * qt);
        u32 wf[4][4];
#pragma unroll
        for (int n8 = 0; n8 < 8; n8++) {
            int kg = kt * 64 + n8 * 8 + (lane & 3) * 2;
            float e0 = fmaxf(fmaf(s[n8][0], SCALE, 0.1f), 0.f);
            float e1 = fmaxf(fmaf(s[n8][1], SCALE, 0.1f), 0.f);
            float e2 = fmaxf(fmaf(s[n8][2], SCALE, 0.1f), 0.f);
            float e3 = fmaxf(fmaf(s[n8][3], SCALE, 0.1f), 0.f);
            if (diag) {
                if (kg     > r0) e0 = 0.f;
                if (kg + 1 > r0) e1 = 0.f;
                if (kg     > r1) e2 = 0.f;
                if (kg + 1 > r1) e3 = 0.f;
            }
            rs0 += e0 + e1;
            rs1 += e2 + e3;
            s[n8][0] = e0; s[n8][1] = e1; s[n8][2] = e2; s[n8][3] = e3;
        }
#pragma unroll
        for (int t = 0; t < 4; t++) {
            wf[t][0] = pack_f16x2(s[2 * t][0],     s[2 * t][1]);
            wf[t][1] = pack_f16x2(s[2 * t][2],     s[2 * t][3]);
            wf[t][2] = pack_f16x2(s[2 * t + 1][0], s[2 * t + 1][1]);
            wf[t][3] = pack_f16x2(s[2 * t + 1][2], s[2 * t + 1][3]);
        }

        // ---- O += W V (fp16, warp: 16 x 128, k = 64)
#pragma unroll
        for (int t = 0; t < 4; t++) {
#pragma unroll
            for (int d2 = 0; d2 < 8; d2++) {
                u32 vb[4];
                int row = t * 16 + (lane & 15);
                int col = d2 * 16 + (lane >> 4) * 8;
                ldsm_x4_t(vb[0], vb[1], vb[2], vb[3], cV + (row * AT_STR + col) * 2);
                u32 b0[2] = { vb[0], vb[1] };
                u32 b1[2] = { vb[2], vb[3] };
                mma16816h(o[2 * d2],     wf[t], b0);
                mma16816h(o[2 * d2 + 1], wf[t], b1);
            }
        }
        if (++st == 3) st = 0;
    }

    // ---- rowsum reduce, normalize, store fp16
    rs0 += __shfl_xor_sync(0xffffffffu, rs0, 1);
    rs0 += __shfl_xor_sync(0xffffffffu, rs0, 2);
    rs1 += __shfl_xor_sync(0xffffffffu, rs1, 1);
    rs1 += __shfl_xor_sync(0xffffffffu, rs1, 2);
    const float inv0 = 1.f / (rs0 + EPSv);
    const float inv1 = 1.f / (rs1 + EPSv);

    const int b  = bh >> 4, hh = bh & 15;
    const size_t base0 = ((size_t)(b * Tn + r0) * Cn) + hh * 128;
    const size_t base1 = ((size_t)(b * Tn + r1) * Cn) + hh * 128;

#pragma unroll
    for (int d8 = 0; d8 < 16; d8++) {
        int col = d8 * 8 + (lane & 3) * 2;
        float v0 = o[d8][0] * inv0, v1 = o[d8][1] * inv0;
        float u0 = o[d8][2] * inv1, u1 = o[d8][3] * inv1;
        *(u32*)&g_Ah[base0 + col] = pack_f16x2(v0, v1);
        *(u32*)&g_Ah[base1 + col] = pack_f16x2(u0, u1);
    }
}

// ---------------------------------------------------------------------------

extern "C" void kernel_launch(void* const* d_in, const int* in_sizes, int n_in,
                              void* d_out, int out_size)
{
    const float* x  = (const float*)d_in[0];
    const float* Wq = (const float*)d_in[1];
    const float* Wk = (const float*)d_in[2];
    const float* Wv = (const float*)d_in[3];
    const float* Wo = (const float*)d_in[4];
    float* out = (float*)d_out;

    cudaFuncSetAttribute(gemm_f16,
                         cudaFuncAttributeMaxDynamicSharedMemorySize, GEMM_SMEM);
    cudaFuncSetAttribute(attn_hmma,
                         cudaFuncAttributeMaxDynamicSharedMemorySize, ATTN_SMEM);

    const int nW4 = (Cn * Cn) / 4;
    const int nX4 = (Bn * Tn * Cn) / 4;
    const int totalPrep = 4 * nW4 + nX4;
    prep_kernel<<<(totalPrep + 255) / 256, 256>>>(x, Wq, Wk, Wv, Wo);

    dim3 gQKV(Cn / 128, (Bn * Tn) / 128, 3);
    gemm_f16<<<gQKV, 256, GEMM_SMEM>>>(0, nullptr);

    dim3 gAttn(Tn / 128, Bn * Hn);
    attn_hmma<<<gAttn, 256, ATTN_SMEM>>>();

    dim3 gOut(Cn / 128, (Bn * Tn) / 128, 1);
    gemm_f16<<<gOut, 256, GEMM_SMEM>>>(1, out);
}

// round 15
// speedup vs baseline: 1.0639x; 1.0639x over previous
#include <cuda_runtime.h>
#include <cuda_bf16.h>
#include <cuda_fp16.h>

typedef unsigned int       u32;
typedef unsigned long long u64;

// Problem constants
constexpr int Bn  = 2;
constexpr int Tn  = 2048;
constexpr int Cn  = 2048;
constexpr int Hn  = 16;
constexpr int HDn = 128;
constexpr float SCALE = 0.088388347648318447f;   // 1/sqrt(128)
constexpr float EPSv  = 1e-6f;

// ---------------------------------------------------------------------------
// Device-global scratch (all activations fp16)
// ---------------------------------------------------------------------------
__device__ __half g_Qh [(size_t)Bn * Hn * Tn * HDn];  // [B,H,T,hd]
__device__ __half g_Kh [(size_t)Bn * Hn * Tn * HDn];
__device__ __half g_Vh [(size_t)Bn * Hn * Tn * HDn];

__device__ __half g_Xh [(size_t)Bn * Tn * Cn];
__device__ __half g_Wh[4][(size_t)Cn * Cn];
__device__ __half g_Ah [(size_t)Bn * Tn * Cn];        // attn out fp16

// ---------------------------------------------------------------------------
// PTX helpers
// ---------------------------------------------------------------------------
__device__ __forceinline__ u32 smem_to_u32(const void* p) {
    u32 a;
    asm("{ .reg .u64 t; cvta.to.shared.u64 t, %1; cvt.u32.u64 %0, t; }"
        : "=r"(a) : "l"(p));
    return a;
}

__device__ __forceinline__ void cp16(u32 saddr, const void* g) {
    asm volatile("cp.async.cg.shared.global [%0], [%1], 16;"
                 :: "r"(saddr), "l"(g) : "memory");
}
#define CP_COMMIT() asm volatile("cp.async.commit_group;" ::: "memory")
#define CP_WAIT(n)  asm volatile("cp.async.wait_group %0;" :: "n"(n) : "memory")

__device__ __forceinline__ void ldsm_x4(u32& r0, u32& r1, u32& r2, u32& r3, u32 addr) {
    asm volatile("ldmatrix.sync.aligned.m8n8.x4.shared.b16 {%0,%1,%2,%3}, [%4];"
                 : "=r"(r0), "=r"(r1), "=r"(r2), "=r"(r3) : "r"(addr));
}
__device__ __forceinline__ void ldsm_x4_t(u32& r0, u32& r1, u32& r2, u32& r3, u32 addr) {
    asm volatile("ldmatrix.sync.aligned.m8n8.x4.trans.shared.b16 {%0,%1,%2,%3}, [%4];"
                 : "=r"(r0), "=r"(r1), "=r"(r2), "=r"(r3) : "r"(addr));
}

__device__ __forceinline__ void mma16816h(float* d, const u32* a, const u32* b) {
    asm volatile(
        "mma.sync.aligned.m16n8k16.row.col.f32.f16.f16.f32 "
        "{%0,%1,%2,%3}, {%4,%5,%6,%7}, {%8,%9}, {%0,%1,%2,%3};"
        : "+f"(d[0]), "+f"(d[1]), "+f"(d[2]), "+f"(d[3])
        : "r"(a[0]), "r"(a[1]), "r"(a[2]), "r"(a[3]), "r"(b[0]), "r"(b[1]));
}

// pack {lo, hi} floats (lo -> bits[15:0])
__device__ __forceinline__ u32 pack_f16x2(float lo, float hi) {
    u32 r;
    asm("cvt.rn.f16x2.f32 %0, %1, %2;" : "=r"(r) : "f"(hi), "f"(lo));
    return r;
}

// ---------------------------------------------------------------------------
// Fused prologue: convert Wq/Wk/Wv/Wo and X to fp16 (single launch).
// ---------------------------------------------------------------------------
__global__ void prep_kernel(const float* __restrict__ x,
                            const float* __restrict__ Wq,
                            const float* __restrict__ Wk,
                            const float* __restrict__ Wv,
                            const float* __restrict__ Wo)
{
    const int nW4 = (Cn * Cn) / 4;
    const int nX4 = (Bn * Tn * Cn) / 4;
    const int total = 4 * nW4 + nX4;
    int g = blockIdx.x * blockDim.x + threadIdx.x;
    if (g >= total) return;

    const float* in;
    __half* dst;
    int i;
    if (g < 4 * nW4) {
        int which = g / nW4;
        i = (g - which * nW4) * 4;
        in = (which == 0) ? Wq : (which == 1) ? Wk : (which == 2) ? Wv : Wo;
        dst = g_Wh[which];
    } else {
        i = (g - 4 * nW4) * 4;
        in = x;
        dst = g_Xh;
    }
    float4 v = *(const float4*)(in + i);
    __half2* p = (__half2*)(dst + i);
    p[0] = __halves2half2(__float2half(v.x), __float2half(v.y));
    p[1] = __halves2half2(__float2half(v.z), __float2half(v.w));
}

// ---------------------------------------------------------------------------
// HMMA fp16 single-pass GEMM (R13 structure + chunk-wide frag prefetch):
// out[m,n] = sum_k A[m,k] * W[n,k]
// Block 128x128, BK=32, 8 warps (2x4), warp tile 64x32, double-buffered,
// 2 CTAs/SM. All 12 ldsm of a chunk are issued before the 32 mma.
// isOut==0: A=Xh, B=W[z]; out -> Qh (z=0), Kh (z=1), Vh (z=2), [B,H,T,hd]
// isOut==1: A=g_Ah, B=Wo; out -> fp32 OutParam
// ---------------------------------------------------------------------------
constexpr int GBK     = 32;
constexpr int LDS_H   = 40;
constexpr int TILE_B  = 128 * LDS_H * 2;          // 10240
constexpr int STAGE_B = 2 * TILE_B;               // 20480
constexpr int GEMM_SMEM = 2 * STAGE_B;            // 40960
constexpr int NCHUNK  = Cn / GBK;                 // 64

__global__ __launch_bounds__(256, 2)
void gemm_f16(int isOut, float* __restrict__ OutParam)
{
    extern __shared__ char smem[];
    const u32 sbase = smem_to_u32(smem);
    const int tid  = threadIdx.x;
    const int lane = tid & 31;
    const int warp = tid >> 5;
    const int wr   = warp >> 2;     // 0..1
    const int wc   = warp & 3;      // 0..3

    const int mat = isOut ? 3 : blockIdx.z;
    const __half* __restrict__ Am = isOut ? g_Ah : g_Xh;
    const __half* __restrict__ Bm = g_Wh[mat];

    const int mBase = blockIdx.y * 128;
    const int nBase = blockIdx.x * 128;

    float acc[4][4][4];
#pragma unroll
    for (int i = 0; i < 4; i++)
#pragma unroll
        for (int j = 0; j < 4; j++)
#pragma unroll
            for (int r = 0; r < 4; r++) acc[i][j][r] = 0.f;

    const int ldr = tid >> 1;
    const int ldc = (tid & 1) * 16;

    auto load_chunk = [&](int kc, int s) {
        const u32 sb = sbase + s * STAGE_B;
        const int k0 = kc * GBK;
        {
            const __half* g = Am + (size_t)(mBase + ldr) * Cn + k0 + ldc;
            u32 sa = sb + (ldr * LDS_H + ldc) * 2;
            cp16(sa,      g);
            cp16(sa + 16, g + 8);
        }
        {
            const __half* g = Bm + (size_t)(nBase + ldr) * Cn + k0 + ldc;
            u32 sa = sb + TILE_B + (ldr * LDS_H + ldc) * 2;
            cp16(sa,      g);
            cp16(sa + 16, g + 8);
        }
        CP_COMMIT();
    };

    load_chunk(0, 0);

    for (int c = 0; c < NCHUNK; c++) {
        const int s = c & 1;
        if (c + 1 < NCHUNK) load_chunk(c + 1, s ^ 1);
        if (c + 1 < NCHUNK) { CP_WAIT(1); } else { CP_WAIT(0); }
        __syncthreads();

        const u32 sb = sbase + s * STAGE_B;
        const u32 sA = sb;
        const u32 sB = sb + TILE_B;

        // ---- chunk-wide fragment prefetch: all 12 ldsm before any mma
        u32 af[2][4][4], bfr[2][2][4];
#pragma unroll
        for (int k16 = 0; k16 < 2; k16++) {
            const int col = k16 * 16 + (lane >> 4) * 8;
            const int lrow = (lane & 15);
#pragma unroll
            for (int mt = 0; mt < 4; mt++) {
                int row = wr * 64 + mt * 16 + lrow;
                u32 off = (u32)(row * LDS_H + col) * 2;
                ldsm_x4(af[k16][mt][0], af[k16][mt][1],
                        af[k16][mt][2], af[k16][mt][3], sA + off);
            }
#pragma unroll
            for (int p = 0; p < 2; p++) {
                int row = wc * 32 + p * 16 + lrow;
                u32 off = (u32)(row * LDS_H + col) * 2;
                ldsm_x4(bfr[k16][p][0], bfr[k16][p][1],
                        bfr[k16][p][2], bfr[k16][p][3], sB + off);
            }
        }

        // ---- mma, k16-major (same summation order as R13)
#pragma unroll
        for (int k16 = 0; k16 < 2; k16++) {
            u32 b0[2][2], b1[2][2];
#pragma unroll
            for (int p = 0; p < 2; p++) {
                b0[p][0] = bfr[k16][p][0]; b0[p][1] = bfr[k16][p][2];
                b1[p][0] = bfr[k16][p][1]; b1[p][1] = bfr[k16][p][3];
            }
#pragma unroll
            for (int mt = 0; mt < 4; mt++)
#pragma unroll
                for (int p = 0; p < 2; p++) {
                    mma16816h(acc[mt][2 * p],     af[k16][mt], b0[p]);
                    mma16816h(acc[mt][2 * p + 1], af[k16][mt], b1[p]);
                }
        }
        __syncthreads();
    }

    // ---- epilogue: two 64-col half passes through smem
    float* sD = (float*)smem;   // [128][68] = 34816 B
    const int c2  = (tid & 31) * 2;
    const int rr0 = tid >> 5;   // 0..7

#pragma unroll
    for (int hc = 0; hc < 2; hc++) {
        __syncthreads();
        if ((wc >> 1) == hc) {
#pragma unroll
            for (int mt = 0; mt < 4; mt++)
#pragma unroll
                for (int nt = 0; nt < 4; nt++) {
                    int row = wr * 64 + mt * 16 + (lane >> 2);
                    int col = (wc & 1) * 32 + nt * 8 + (lane & 3) * 2;
                    sD[row * 68 + col + 0]       = acc[mt][nt][0];
                    sD[row * 68 + col + 1]       = acc[mt][nt][1];
                    sD[(row + 8) * 68 + col + 0] = acc[mt][nt][2];
                    sD[(row + 8) * 68 + col + 1] = acc[mt][nt][3];
                }
        }
        __syncthreads();

        if (!isOut) {
            __half* O = (mat == 0) ? g_Qh : (mat == 1) ? g_Kh : g_Vh;
            const int h = blockIdx.x;      // BN == hd == 128
            const int d = hc * 64 + c2;
#pragma unroll 4
            for (int rr = 0; rr < 16; rr++) {
                int r = rr * 8 + rr0;
                int m = mBase + r;
                int b = m >> 11, t = m & (Tn - 1);
                size_t idx = (size_t)((b * Hn + h) * Tn + t) * HDn + d;
                *(u32*)&O[idx] = pack_f16x2(sD[r * 68 + c2], sD[r * 68 + c2 + 1]);
            }
        } else {
#pragma unroll 4
            for (int rr = 0; rr < 16; rr++) {
                int r = rr * 8 + rr0;
                int m = mBase + r;
                float2 v = make_float2(sD[r * 68 + c2], sD[r * 68 + c2 + 1]);
                *(float2*)&OutParam[(size_t)m * Cn + nBase + hc * 64 + c2] = v;
            }
        }
    }
}

// ---------------------------------------------------------------------------
// HMMA fused relu-attention (R13 version, unchanged).
// S = Q K^T; W(fp16) @ V(fp16). Q fragments hoisted out of the kt loop.
// Block: 128 q-rows x (b,h). 8 warps x 16 q-rows. 64-row K/V tiles, dbl-buf.
// ---------------------------------------------------------------------------
constexpr int AT_STR  = 136;
constexpr int AT_Q_B  = 128 * AT_STR * 2;                 // 34816
constexpr int AT_KV_B = 64 * AT_STR * 2;                  // 17408
constexpr int ATTN_SMEM = AT_Q_B + 4 * AT_KV_B;           // 104448

__global__ __launch_bounds__(256, 1)
void attn_hmma()
{
    extern __shared__ char smem[];
    const u32 sQ  = smem_to_u32(smem);
    const u32 sS0 = sQ + AT_Q_B;
    const u32 sS1 = sS0 + 2 * AT_KV_B;

    const int tid  = threadIdx.x;
    const int lane = tid & 31;
    const int w    = tid >> 5;

    const int qt  = (gridDim.x - 1) - blockIdx.x;
    const int bh  = blockIdx.y;
    const int qg0 = qt * 128;

    const __half* Qg = g_Qh + ((size_t)bh * Tn + qg0) * HDn;
    const __half* Kg = g_Kh + (size_t)bh * Tn * HDn;
    const __half* Vg = g_Vh + (size_t)bh * Tn * HDn;

    auto load_kv = [&](int kt, u32 st) {
        const int kr = tid >> 2, kseg = (tid & 3) * 32;
        const size_t gro = (size_t)(kt * 64 + kr) * HDn;
        const u32 so = (kr * AT_STR + kseg) * 2;
#pragma unroll
        for (int i = 0; i < 4; i++) {
            int c = i * 8;
            cp16(st + so + c * 2,            Kg + gro + kseg + c);
            cp16(st + AT_KV_B + so + c * 2,  Vg + gro + kseg + c);
        }
        CP_COMMIT();
    };

    // ---- prologue: Q, then KV tile 0
    {
        const int r = tid >> 1, cseg = (tid & 1) * 64;
#pragma unroll
        for (int i = 0; i < 8; i++) {
            int col = cseg + i * 8;
            cp16(sQ + (r * AT_STR + col) * 2, Qg + (size_t)r * HDn + col);
        }
        CP_COMMIT();
    }
    load_kv(0, sS0);

    CP_WAIT(1);
    __syncthreads();

    u32 qf[8][4];
    {
        const int row = w * 16 + (lane & 15);
#pragma unroll
        for (int c16 = 0; c16 < 8; c16++) {
            int col = c16 * 16 + (lane >> 4) * 8;
            u32 off = (u32)(row * AT_STR + col) * 2;
            ldsm_x4(qf[c16][0], qf[c16][1], qf[c16][2], qf[c16][3], sQ + off);
        }
    }

    const int ktmax = 2 * qt + 1;

    float o[16][4];
#pragma unroll
    for (int i = 0; i < 16; i++)
#pragma unroll
        for (int r = 0; r < 4; r++) o[i][r] = 0.f;
    float rs0 = 0.f, rs1 = 0.f;

    const int r0 = qg0 + w * 16 + (lane >> 2);
    const int r1 = r0 + 8;

    for (int kt = 0; kt <= ktmax; kt++) {
        if (kt + 1 <= ktmax) {
            load_kv(kt + 1, ((kt + 1) & 1) ? sS1 : sS0);
            CP_WAIT(1);
        } else {
            CP_WAIT(0);
        }
        __syncthreads();

        const u32 st = (kt & 1) ? sS1 : sS0;
        const u32 cK = st;
        const u32 cV = st + AT_KV_B;

        // ---- S = Q K^T (single fp16 pass), warp: 16 x 64
        float s[8][4];
#pragma unroll
        for (int i = 0; i < 8; i++)
#pragma unroll
            for (int r = 0; r < 4; r++) s[i][r] = 0.f;

#pragma unroll
        for (int c16 = 0; c16 < 8; c16++) {
            u32 kb[4][4];
#pragma unroll
            for (int np = 0; np < 4; np++) {
                int row = np * 16 + (lane & 15);
                int col = c16 * 16 + (lane >> 4) * 8;
                u32 off = (u32)(row * AT_STR + col) * 2;
                ldsm_x4(kb[np][0], kb[np][1], kb[np][2], kb[np][3], cK + off);
            }
            u32 b2[8][2];
#pragma unroll
            for (int np = 0; np < 4; np++) {
                b2[2 * np][0]     = kb[np][0]; b2[2 * np][1]     = kb[np][2];
                b2[2 * np + 1][0] = kb[np][1]; b2[2 * np + 1][1] = kb[np][3];
            }
#pragma unroll
            for (int t = 0; t < 8; t++) mma16816h(s[t], qf[c16], b2[t]);
        }

        // ---- relu + mask + rowsum; pack as fp16 A-frags
        const bool diag = (kt >= 2 * qt);
        u32 wf[4][4];
#pragma unroll
        for (int n8 = 0; n8 < 8; n8++) {
            int kg = kt * 64 + n8 * 8 + (lane & 3) * 2;
            float e0 = fmaxf(fmaf(s[n8][0], SCALE, 0.1f), 0.f);
            float e1 = fmaxf(fmaf(s[n8][1], SCALE, 0.1f), 0.f);
            float e2 = fmaxf(fmaf(s[n8][2], SCALE, 0.1f), 0.f);
            float e3 = fmaxf(fmaf(s[n8][3], SCALE, 0.1f), 0.f);
            if (diag) {
                if (kg     > r0) e0 = 0.f;
                if (kg + 1 > r0) e1 = 0.f;
                if (kg     > r1) e2 = 0.f;
                if (kg + 1 > r1) e3 = 0.f;
            }
            rs0 += e0 + e1;
            rs1 += e2 + e3;
            s[n8][0] = e0; s[n8][1] = e1; s[n8][2] = e2; s[n8][3] = e3;
        }
#pragma unroll
        for (int t = 0; t < 4; t++) {
            wf[t][0] = pack_f16x2(s[2 * t][0],     s[2 * t][1]);
            wf[t][1] = pack_f16x2(s[2 * t][2],     s[2 * t][3]);
            wf[t][2] = pack_f16x2(s[2 * t + 1][0], s[2 * t + 1][1]);
            wf[t][3] = pack_f16x2(s[2 * t + 1][2], s[2 * t + 1][3]);
        }

        // ---- O += W V (fp16, warp: 16 x 128, k = 64)
#pragma unroll
        for (int t = 0; t < 4; t++) {
#pragma unroll
            for (int d2 = 0; d2 < 8; d2++) {
                u32 vb[4];
                int row = t * 16 + (lane & 15);
                int col = d2 * 16 + (lane >> 4) * 8;
                ldsm_x4_t(vb[0], vb[1], vb[2], vb[3], cV + (row * AT_STR + col) * 2);
                u32 b0[2] = { vb[0], vb[1] };
                u32 b1[2] = { vb[2], vb[3] };
                mma16816h(o[2 * d2],     wf[t], b0);
                mma16816h(o[2 * d2 + 1], wf[t], b1);
            }
        }
        __syncthreads();
    }

    // ---- rowsum reduce, normalize, store fp16
    rs0 += __shfl_xor_sync(0xffffffffu, rs0, 1);
    rs0 += __shfl_xor_sync(0xffffffffu, rs0, 2);
    rs1 += __shfl_xor_sync(0xffffffffu, rs1, 1);
    rs1 += __shfl_xor_sync(0xffffffffu, rs1, 2);
    const float inv0 = 1.f / (rs0 + EPSv);
    const float inv1 = 1.f / (rs1 + EPSv);

    const int b  = bh >> 4, hh = bh & 15;
    const size_t base0 = ((size_t)(b * Tn + r0) * Cn) + hh * 128;
    const size_t base1 = ((size_t)(b * Tn + r1) * Cn) + hh * 128;

#pragma unroll
    for (int d8 = 0; d8 < 16; d8++) {
        int col = d8 * 8 + (lane & 3) * 2;
        float v0 = o[d8][0] * inv0, v1 = o[d8][1] * inv0;
        float u0 = o[d8][2] * inv1, u1 = o[d8][3] * inv1;
        *(u32*)&g_Ah[base0 + col] = pack_f16x2(v0, v1);
        *(u32*)&g_Ah[base1 + col] = pack_f16x2(u0, u1);
    }
}

// ---------------------------------------------------------------------------

extern "C" void kernel_launch(void* const* d_in, const int* in_sizes, int n_in,
                              void* d_out, int out_size)
{
    const float* x  = (const float*)d_in[0];
    const float* Wq = (const float*)d_in[1];
    const float* Wk = (const float*)d_in[2];
    const float* Wv = (const float*)d_in[3];
    const float* Wo = (const float*)d_in[4];
    float* out = (float*)d_out;

    cudaFuncSetAttribute(gemm_f16,
                         cudaFuncAttributeMaxDynamicSharedMemorySize, GEMM_SMEM);
    cudaFuncSetAttribute(attn_hmma,
                         cudaFuncAttributeMaxDynamicSharedMemorySize, ATTN_SMEM);

    const int nW4 = (Cn * Cn) / 4;
    const int nX4 = (Bn * Tn * Cn) / 4;
    const int totalPrep = 4 * nW4 + nX4;
    prep_kernel<<<(totalPrep + 255) / 256, 256>>>(x, Wq, Wk, Wv, Wo);

    dim3 gQKV(Cn / 128, (Bn * Tn) / 128, 3);
    gemm_f16<<<gQKV, 256, GEMM_SMEM>>>(0, nullptr);

    dim3 gAttn(Tn / 128, Bn * Hn);
    attn_hmma<<<gAttn, 256, ATTN_SMEM>>>();

    dim3 gOut(Cn / 128, (Bn * Tn) / 128, 1);
    gemm_f16<<<gOut, 256, GEMM_SMEM>>>(1, out);
}

// round 16
// speedup vs baseline: 1.0666x; 1.0025x over previous
#include <cuda_runtime.h>
#include <cuda_bf16.h>
#include <cuda_fp16.h>

typedef unsigned int       u32;
typedef unsigned long long u64;

// Problem constants
constexpr int Bn  = 2;
constexpr int Tn  = 2048;
constexpr int Cn  = 2048;
constexpr int Hn  = 16;
constexpr int HDn = 128;
constexpr float SCALE = 0.088388347648318447f;   // 1/sqrt(128)
constexpr float EPSv  = 1e-6f;

// ---------------------------------------------------------------------------
// Device-global scratch (all activations fp16)
// ---------------------------------------------------------------------------
__device__ __half g_Qh [(size_t)Bn * Hn * Tn * HDn];  // [B,H,T,hd]
__device__ __half g_Kh [(size_t)Bn * Hn * Tn * HDn];
__device__ __half g_Vh [(size_t)Bn * Hn * Tn * HDn];

__device__ __half g_Xh [(size_t)Bn * Tn * Cn];
__device__ __half g_Wh[4][(size_t)Cn * Cn];
__device__ __half g_Ah [(size_t)Bn * Tn * Cn];        // attn out fp16

// ---------------------------------------------------------------------------
// PTX helpers
// ---------------------------------------------------------------------------
__device__ __forceinline__ u32 smem_to_u32(const void* p) {
    u32 a;
    asm("{ .reg .u64 t; cvta.to.shared.u64 t, %1; cvt.u32.u64 %0, t; }"
        : "=r"(a) : "l"(p));
    return a;
}

__device__ __forceinline__ void cp16(u32 saddr, const void* g) {
    asm volatile("cp.async.cg.shared.global [%0], [%1], 16;"
                 :: "r"(saddr), "l"(g) : "memory");
}
#define CP_COMMIT() asm volatile("cp.async.commit_group;" ::: "memory")
#define CP_WAIT(n)  asm volatile("cp.async.wait_group %0;" :: "n"(n) : "memory")

__device__ __forceinline__ void ldsm_x4(u32& r0, u32& r1, u32& r2, u32& r3, u32 addr) {
    asm volatile("ldmatrix.sync.aligned.m8n8.x4.shared.b16 {%0,%1,%2,%3}, [%4];"
                 : "=r"(r0), "=r"(r1), "=r"(r2), "=r"(r3) : "r"(addr));
}
__device__ __forceinline__ void ldsm_x4_t(u32& r0, u32& r1, u32& r2, u32& r3, u32 addr) {
    asm volatile("ldmatrix.sync.aligned.m8n8.x4.trans.shared.b16 {%0,%1,%2,%3}, [%4];"
                 : "=r"(r0), "=r"(r1), "=r"(r2), "=r"(r3) : "r"(addr));
}

__device__ __forceinline__ void mma16816h(float* d, const u32* a, const u32* b) {
    asm volatile(
        "mma.sync.aligned.m16n8k16.row.col.f32.f16.f16.f32 "
        "{%0,%1,%2,%3}, {%4,%5,%6,%7}, {%8,%9}, {%0,%1,%2,%3};"
        : "+f"(d[0]), "+f"(d[1]), "+f"(d[2]), "+f"(d[3])
        : "r"(a[0]), "r"(a[1]), "r"(a[2]), "r"(a[3]), "r"(b[0]), "r"(b[1]));
}

// pack {lo, hi} floats (lo -> bits[15:0])
__device__ __forceinline__ u32 pack_f16x2(float lo, float hi) {
    u32 r;
    asm("cvt.rn.f16x2.f32 %0, %1, %2;" : "=r"(r) : "f"(hi), "f"(lo));
    return r;
}

// ---------------------------------------------------------------------------
// Fused prologue: convert Wq/Wk/Wv/Wo and X to fp16 (single launch).
// ---------------------------------------------------------------------------
__global__ void prep_kernel(const float* __restrict__ x,
                            const float* __restrict__ Wq,
                            const float* __restrict__ Wk,
                            const float* __restrict__ Wv,
                            const float* __restrict__ Wo)
{
    const int nW4 = (Cn * Cn) / 4;
    const int nX4 = (Bn * Tn * Cn) / 4;
    const int total = 4 * nW4 + nX4;
    int g = blockIdx.x * blockDim.x + threadIdx.x;
    if (g >= total) return;

    const float* in;
    __half* dst;
    int i;
    if (g < 4 * nW4) {
        int which = g / nW4;
        i = (g - which * nW4) * 4;
        in = (which == 0) ? Wq : (which == 1) ? Wk : (which == 2) ? Wv : Wo;
        dst = g_Wh[which];
    } else {
        i = (g - 4 * nW4) * 4;
        in = x;
        dst = g_Xh;
    }
    float4 v = *(const float4*)(in + i);
    __half2* p = (__half2*)(dst + i);
    p[0] = __halves2half2(__float2half(v.x), __float2half(v.y));
    p[1] = __halves2half2(__float2half(v.z), __float2half(v.w));
}

// ---------------------------------------------------------------------------
// HMMA fp16 single-pass GEMM, occupancy-optimized:
// CTA tile 128x64, BK=32, 8 warps (4x2), warp tile 32x32, double-buffered,
// 3 CTAs/SM (24 warps/SM).
// isOut==0: A=Xh, B=W[z]; out -> Qh (z=0), Kh (z=1), Vh (z=2), [B,H,T,hd]
// isOut==1: A=g_Ah, B=Wo; out -> fp32 OutParam
// ---------------------------------------------------------------------------
constexpr int GBK     = 32;
constexpr int LDS_H   = 40;                       // halves per row (32+8)
constexpr int TILE_A  = 128 * LDS_H * 2;          // 10240
constexpr int TILE_BB = 64 * LDS_H * 2;           // 5120
constexpr int STAGE_B = TILE_A + TILE_BB;         // 15360
constexpr int GEMM_SMEM = 34816;                  // max(2*STAGE_B=30720, sD 128*68*4)
constexpr int NCHUNK  = Cn / GBK;                 // 64

__global__ __launch_bounds__(256, 3)
void gemm_f16(int isOut, float* __restrict__ OutParam)
{
    extern __shared__ char smem[];
    const u32 sbase = smem_to_u32(smem);
    const int tid  = threadIdx.x;
    const int lane = tid & 31;
    const int warp = tid >> 5;
    const int wr   = warp >> 1;     // 0..3 : 32-row group
    const int wc   = warp & 1;      // 0..1 : 32-col group

    const int mat = isOut ? 3 : blockIdx.z;
    const __half* __restrict__ Am = isOut ? g_Ah : g_Xh;
    const __half* __restrict__ Bm = g_Wh[mat];

    const int mBase = blockIdx.y * 128;
    const int nBase = blockIdx.x * 64;

    float acc[2][4][4];
#pragma unroll
    for (int i = 0; i < 2; i++)
#pragma unroll
        for (int j = 0; j < 4; j++)
#pragma unroll
            for (int r = 0; r < 4; r++) acc[i][j][r] = 0.f;

    // A loader: 2 threads per row, 16 halves each. B loader: 4 threads/row, 8 halves.
    const int ldrA = tid >> 1;
    const int ldcA = (tid & 1) * 16;
    const int ldrB = tid >> 2;
    const int ldcB = (tid & 3) * 8;

    auto load_chunk = [&](int kc, int s) {
        const u32 sb = sbase + s * STAGE_B;
        const int k0 = kc * GBK;
        {
            const __half* g = Am + (size_t)(mBase + ldrA) * Cn + k0 + ldcA;
            u32 sa = sb + (ldrA * LDS_H + ldcA) * 2;
            cp16(sa,      g);
            cp16(sa + 16, g + 8);
        }
        {
            const __half* g = Bm + (size_t)(nBase + ldrB) * Cn + k0 + ldcB;
            cp16(sb + TILE_A + (ldrB * LDS_H + ldcB) * 2, g);
        }
        CP_COMMIT();
    };

    load_chunk(0, 0);

    for (int c = 0; c < NCHUNK; c++) {
        const int s = c & 1;
        if (c + 1 < NCHUNK) load_chunk(c + 1, s ^ 1);
        if (c + 1 < NCHUNK) { CP_WAIT(1); } else { CP_WAIT(0); }
        __syncthreads();

        const u32 sb = sbase + s * STAGE_B;
        const u32 sA = sb;
        const u32 sB = sb + TILE_A;

#pragma unroll
        for (int k16 = 0; k16 < 2; k16++) {
            const int col = k16 * 16 + (lane >> 4) * 8;
            const int lrow = (lane & 15);

            u32 af[2][4], bfr[2][4];
#pragma unroll
            for (int mt = 0; mt < 2; mt++) {
                int row = wr * 32 + mt * 16 + lrow;
                u32 off = (u32)(row * LDS_H + col) * 2;
                ldsm_x4(af[mt][0], af[mt][1], af[mt][2], af[mt][3], sA + off);
            }
#pragma unroll
            for (int p = 0; p < 2; p++) {
                int row = wc * 32 + p * 16 + lrow;
                u32 off = (u32)(row * LDS_H + col) * 2;
                ldsm_x4(bfr[p][0], bfr[p][1], bfr[p][2], bfr[p][3], sB + off);
            }
            u32 b0[2][2], b1[2][2];
#pragma unroll
            for (int p = 0; p < 2; p++) {
                b0[p][0] = bfr[p][0]; b0[p][1] = bfr[p][2];
                b1[p][0] = bfr[p][1]; b1[p][1] = bfr[p][3];
            }
#pragma unroll
            for (int mt = 0; mt < 2; mt++)
#pragma unroll
                for (int p = 0; p < 2; p++) {
                    mma16816h(acc[mt][2 * p],     af[mt], b0[p]);
                    mma16816h(acc[mt][2 * p + 1], af[mt], b1[p]);
                }
        }
        __syncthreads();
    }

    // ---- epilogue: single pass through smem (all warps disjoint 32x32)
    float* sD = (float*)smem;   // [128][68] = 34816 B
    __syncthreads();
#pragma unroll
    for (int mt = 0; mt < 2; mt++)
#pragma unroll
        for (int nt = 0; nt < 4; nt++) {
            int row = wr * 32 + mt * 16 + (lane >> 2);
            int col = wc * 32 + nt * 8 + (lane & 3) * 2;
            sD[row * 68 + col + 0]       = acc[mt][nt][0];
            sD[row * 68 + col + 1]       = acc[mt][nt][1];
            sD[(row + 8) * 68 + col + 0] = acc[mt][nt][2];
            sD[(row + 8) * 68 + col + 1] = acc[mt][nt][3];
        }
    __syncthreads();

    const int c2  = (tid & 31) * 2;   // 0..62
    const int rr0 = tid >> 5;         // 0..7
    if (!isOut) {
        __half* O = (mat == 0) ? g_Qh : (mat == 1) ? g_Kh : g_Vh;
        const int gcol = nBase + c2;
        const int h = gcol >> 7;
        const int d = gcol & 127;
#pragma unroll 4
        for (int rr = 0; rr < 16; rr++) {
            int r = rr * 8 + rr0;
            int m = mBase + r;
            int b = m >> 11, t = m & (Tn - 1);
            size_t idx = (size_t)((b * Hn + h) * Tn + t) * HDn + d;
            *(u32*)&O[idx] = pack_f16x2(sD[r * 68 + c2], sD[r * 68 + c2 + 1]);
        }
    } else {
#pragma unroll 4
        for (int rr = 0; rr < 16; rr++) {
            int r = rr * 8 + rr0;
            int m = mBase + r;
            float2 v = make_float2(sD[r * 68 + c2], sD[r * 68 + c2 + 1]);
            *(float2*)&OutParam[(size_t)m * Cn + nBase + c2] = v;
        }
    }
}

// ---------------------------------------------------------------------------
// HMMA fused relu-attention (R13 version, unchanged).
// S = Q K^T; W(fp16) @ V(fp16). Q fragments hoisted out of the kt loop.
// Block: 128 q-rows x (b,h). 8 warps x 16 q-rows. 64-row K/V tiles, dbl-buf.
// ---------------------------------------------------------------------------
constexpr int AT_STR  = 136;
constexpr int AT_Q_B  = 128 * AT_STR * 2;                 // 34816
constexpr int AT_KV_B = 64 * AT_STR * 2;                  // 17408
constexpr int ATTN_SMEM = AT_Q_B + 4 * AT_KV_B;           // 104448

__global__ __launch_bounds__(256, 1)
void attn_hmma()
{
    extern __shared__ char smem[];
    const u32 sQ  = smem_to_u32(smem);
    const u32 sS0 = sQ + AT_Q_B;
    const u32 sS1 = sS0 + 2 * AT_KV_B;

    const int tid  = threadIdx.x;
    const int lane = tid & 31;
    const int w    = tid >> 5;

    const int qt  = (gridDim.x - 1) - blockIdx.x;
    const int bh  = blockIdx.y;
    const int qg0 = qt * 128;

    const __half* Qg = g_Qh + ((size_t)bh * Tn + qg0) * HDn;
    const __half* Kg = g_Kh + (size_t)bh * Tn * HDn;
    const __half* Vg = g_Vh + (size_t)bh * Tn * HDn;

    auto load_kv = [&](int kt, u32 st) {
        const int kr = tid >> 2, kseg = (tid & 3) * 32;
        const size_t gro = (size_t)(kt * 64 + kr) * HDn;
        const u32 so = (kr * AT_STR + kseg) * 2;
#pragma unroll
        for (int i = 0; i < 4; i++) {
            int c = i * 8;
            cp16(st + so + c * 2,            Kg + gro + kseg + c);
            cp16(st + AT_KV_B + so + c * 2,  Vg + gro + kseg + c);
        }
        CP_COMMIT();
    };

    // ---- prologue: Q, then KV tile 0
    {
        const int r = tid >> 1, cseg = (tid & 1) * 64;
#pragma unroll
        for (int i = 0; i < 8; i++) {
            int col = cseg + i * 8;
            cp16(sQ + (r * AT_STR + col) * 2, Qg + (size_t)r * HDn + col);
        }
        CP_COMMIT();
    }
    load_kv(0, sS0);

    CP_WAIT(1);
    __syncthreads();

    u32 qf[8][4];
    {
        const int row = w * 16 + (lane & 15);
#pragma unroll
        for (int c16 = 0; c16 < 8; c16++) {
            int col = c16 * 16 + (lane >> 4) * 8;
            u32 off = (u32)(row * AT_STR + col) * 2;
            ldsm_x4(qf[c16][0], qf[c16][1], qf[c16][2], qf[c16][3], sQ + off);
        }
    }

    const int ktmax = 2 * qt + 1;

    float o[16][4];
#pragma unroll
    for (int i = 0; i < 16; i++)
#pragma unroll
        for (int r = 0; r < 4; r++) o[i][r] = 0.f;
    float rs0 = 0.f, rs1 = 0.f;

    const int r0 = qg0 + w * 16 + (lane >> 2);
    const int r1 = r0 + 8;

    for (int kt = 0; kt <= ktmax; kt++) {
        if (kt + 1 <= ktmax) {
            load_kv(kt + 1, ((kt + 1) & 1) ? sS1 : sS0);
            CP_WAIT(1);
        } else {
            CP_WAIT(0);
        }
        __syncthreads();

        const u32 st = (kt & 1) ? sS1 : sS0;
        const u32 cK = st;
        const u32 cV = st + AT_KV_B;

        // ---- S = Q K^T (single fp16 pass), warp: 16 x 64
        float s[8][4];
#pragma unroll
        for (int i = 0; i < 8; i++)
#pragma unroll
            for (int r = 0; r < 4; r++) s[i][r] = 0.f;

#pragma unroll
        for (int c16 = 0; c16 < 8; c16++) {
            u32 kb[4][4];
#pragma unroll
            for (int np = 0; np < 4; np++) {
                int row = np * 16 + (lane & 15);
                int col = c16 * 16 + (lane >> 4) * 8;
                u32 off = (u32)(row * AT_STR + col) * 2;
                ldsm_x4(kb[np][0], kb[np][1], kb[np][2], kb[np][3], cK + off);
            }
            u32 b2[8][2];
#pragma unroll
            for (int np = 0; np < 4; np++) {
                b2[2 * np][0]     = kb[np][0]; b2[2 * np][1]     = kb[np][2];
                b2[2 * np + 1][0] = kb[np][1]; b2[2 * np + 1][1] = kb[np][3];
            }
#pragma unroll
            for (int t = 0; t < 8; t++) mma16816h(s[t], qf[c16], b2[t]);
        }

        // ---- relu + mask + rowsum; pack as fp16 A-frags
        const bool diag = (kt >= 2 * qt);
        u32 wf[4][4];
#pragma unroll
        for (int n8 = 0; n8 < 8; n8++) {
            int kg = kt * 64 + n8 * 8 + (lane & 3) * 2;
            float e0 = fmaxf(fmaf(s[n8][0], SCALE, 0.1f), 0.f);
            float e1 = fmaxf(fmaf(s[n8][1], SCALE, 0.1f), 0.f);
            float e2 = fmaxf(fmaf(s[n8][2], SCALE, 0.1f), 0.f);
            float e3 = fmaxf(fmaf(s[n8][3], SCALE, 0.1f), 0.f);
            if (diag) {
                if (kg     > r0) e0 = 0.f;
                if (kg + 1 > r0) e1 = 0.f;
                if (kg     > r1) e2 = 0.f;
                if (kg + 1 > r1) e3 = 0.f;
            }
            rs0 += e0 + e1;
            rs1 += e2 + e3;
            s[n8][0] = e0; s[n8][1] = e1; s[n8][2] = e2; s[n8][3] = e3;
        }
#pragma unroll
        for (int t = 0; t < 4; t++) {
            wf[t][0] = pack_f16x2(s[2 * t][0],     s[2 * t][1]);
            wf[t][1] = pack_f16x2(s[2 * t][2],     s[2 * t][3]);
            wf[t][2] = pack_f16x2(s[2 * t + 1][0], s[2 * t + 1][1]);
            wf[t][3] = pack_f16x2(s[2 * t + 1][2], s[2 * t + 1][3]);
        }

        // ---- O += W V (fp16, warp: 16 x 128, k = 64)
#pragma unroll
        for (int t = 0; t < 4; t++) {
#pragma unroll
            for (int d2 = 0; d2 < 8; d2++) {
                u32 vb[4];
                int row = t * 16 + (lane & 15);
                int col = d2 * 16 + (lane >> 4) * 8;
                ldsm_x4_t(vb[0], vb[1], vb[2], vb[3], cV + (row * AT_STR + col) * 2);
                u32 b0[2] = { vb[0], vb[1] };
                u32 b1[2] = { vb[2], vb[3] };
                mma16816h(o[2 * d2],     wf[t], b0);
                mma16816h(o[2 * d2 + 1], wf[t], b1);
            }
        }
        __syncthreads();
    }

    // ---- rowsum reduce, normalize, store fp16
    rs0 += __shfl_xor_sync(0xffffffffu, rs0, 1);
    rs0 += __shfl_xor_sync(0xffffffffu, rs0, 2);
    rs1 += __shfl_xor_sync(0xffffffffu, rs1, 1);
    rs1 += __shfl_xor_sync(0xffffffffu, rs1, 2);
    const float inv0 = 1.f / (rs0 + EPSv);
    const float inv1 = 1.f / (rs1 + EPSv);

    const int b  = bh >> 4, hh = bh & 15;
    const size_t base0 = ((size_t)(b * Tn + r0) * Cn) + hh * 128;
    const size_t base1 = ((size_t)(b * Tn + r1) * Cn) + hh * 128;

#pragma unroll
    for (int d8 = 0; d8 < 16; d8++) {
        int col = d8 * 8 + (lane & 3) * 2;
        float v0 = o[d8][0] * inv0, v1 = o[d8][1] * inv0;
        float u0 = o[d8][2] * inv1, u1 = o[d8][3] * inv1;
        *(u32*)&g_Ah[base0 + col] = pack_f16x2(v0, v1);
        *(u32*)&g_Ah[base1 + col] = pack_f16x2(u0, u1);
    }
}

// ---------------------------------------------------------------------------

extern "C" void kernel_launch(void* const* d_in, const int* in_sizes, int n_in,
                              void* d_out, int out_size)
{
    const float* x  = (const float*)d_in[0];
    const float* Wq = (const float*)d_in[1];
    const float* Wk = (const float*)d_in[2];
    const float* Wv = (const float*)d_in[3];
    const float* Wo = (const float*)d_in[4];
    float* out = (float*)d_out;

    cudaFuncSetAttribute(gemm_f16,
                         cudaFuncAttributeMaxDynamicSharedMemorySize, GEMM_SMEM);
    cudaFuncSetAttribute(attn_hmma,
                         cudaFuncAttributeMaxDynamicSharedMemorySize, ATTN_SMEM);

    const int nW4 = (Cn * Cn) / 4;
    const int nX4 = (Bn * Tn * Cn) / 4;
    const int totalPrep = 4 * nW4 + nX4;
    prep_kernel<<<(totalPrep + 255) / 256, 256>>>(x, Wq, Wk, Wv, Wo);

    dim3 gQKV(Cn / 64, (Bn * Tn) / 128, 3);
    gemm_f16<<<gQKV, 256, GEMM_SMEM>>>(0, nullptr);

    dim3 gAttn(Tn / 128, Bn * Hn);
    attn_hmma<<<gAttn, 256, ATTN_SMEM>>>();

    dim3 gOut(Cn / 64, (Bn * Tn) / 128, 1);
    gemm_f16<<<gOut, 256, GEMM_SMEM>>>(1, out);
}